// round 6
// baseline (speedup 1.0000x reference)
#include <cuda_runtime.h>
#include <cuda_bf16.h>
#include <cstdint>

// Problem constants (match reference)
#define N_ATOMS 200000
#define N_PAIRS 8000000
#define N_CH 4
#define PAIRS_PER_THREAD 4

__device__ __forceinline__ void red4(float4* ptr, float4 v, float wt)
{
    asm volatile("red.global.add.v4.f32 [%0], {%1, %2, %3, %4};"
                 :: "l"(ptr), "f"(v.x * wt), "f"(v.y * wt),
                    "f"(v.z * wt), "f"(v.w * wt) : "memory");
}

// 4 pairs per thread. Vectorized streaming loads for indices/distances,
// 8 independent charge gathers in flight (MLP), then 8 fire-and-forget
// vectorized L2 reductions (red.global.add.v4.f32).
__global__ void __launch_bounds__(256) pair_scatter_kernel(
    const float4* __restrict__ charges,     // N_ATOMS
    const int4*   __restrict__ nbr_idx4,    // N_PAIRS/2 (two pairs per int4)
    const float4* __restrict__ nbr_dist4,   // N_PAIRS/4
    float4*       __restrict__ potential)   // N_ATOMS
{
    int t = blockIdx.x * blockDim.x + threadIdx.x;
    if (t >= N_PAIRS / PAIRS_PER_THREAD) return;

    // Streaming loads (evict-first): these arrays are touched exactly once.
    int4   ab = __ldcs(&nbr_idx4[2 * t]);      // pairs 4t, 4t+1 -> (i0,j0,i1,j1)
    int4   cd = __ldcs(&nbr_idx4[2 * t + 1]);  // pairs 4t+2, 4t+3
    float4 dv = __ldcs(&nbr_dist4[t]);

    float w0 = __fdividef(0.5f, dv.x);
    float w1 = __fdividef(0.5f, dv.y);
    float w2 = __fdividef(0.5f, dv.z);
    float w3 = __fdividef(0.5f, dv.w);

    // Issue all 8 gathers before consuming any (max MLP).
    float4 ci0 = __ldg(&charges[ab.x]);
    float4 cj0 = __ldg(&charges[ab.y]);
    float4 ci1 = __ldg(&charges[ab.z]);
    float4 cj1 = __ldg(&charges[ab.w]);
    float4 ci2 = __ldg(&charges[cd.x]);
    float4 cj2 = __ldg(&charges[cd.y]);
    float4 ci3 = __ldg(&charges[cd.z]);
    float4 cj3 = __ldg(&charges[cd.w]);

    red4(potential + ab.x, cj0, w0);
    red4(potential + ab.y, ci0, w0);
    red4(potential + ab.z, cj1, w1);
    red4(potential + ab.w, ci1, w1);
    red4(potential + cd.x, cj2, w2);
    red4(potential + cd.y, ci2, w2);
    red4(potential + cd.z, cj3, w3);
    red4(potential + cd.w, ci3, w3);
}

extern "C" void kernel_launch(void* const* d_in, const int* in_sizes, int n_in,
                              void* d_out, int out_size)
{
    const float4* charges   = (const float4*)d_in[0];  // N_ATOMS*4 f32
    const int4*   nbr_idx4  = (const int4*)d_in[1];    // N_PAIRS*2 i32
    const float4* nbr_dist4 = (const float4*)d_in[2];  // N_PAIRS f32
    float4*       out       = (float4*)d_out;          // N_ATOMS*4 f32

    // Output is accumulated into; zero it (memset node is graph-capturable).
    cudaMemsetAsync(d_out, 0, (size_t)out_size * sizeof(float));

    const int threads = 256;
    const int nthreads_total = N_PAIRS / PAIRS_PER_THREAD;   // 2,000,000
    const int blocks = (nthreads_total + threads - 1) / threads;
    pair_scatter_kernel<<<blocks, threads>>>(charges, nbr_idx4, nbr_dist4, out);
}

// round 7
// speedup vs baseline: 1.0173x; 1.0173x over previous
#include <cuda_runtime.h>
#include <cuda_bf16.h>
#include <cstdint>

// Problem constants (match reference)
#define N_ATOMS 200000
#define N_PAIRS 8000000
#define N_CH 4
#define PPT 2   // pairs per thread

__device__ __forceinline__ void red4(float4* ptr, float4 v, float wt)
{
    asm volatile("red.global.add.v4.f32 [%0], {%1, %2, %3, %4};"
                 :: "l"(ptr), "f"(v.x * wt), "f"(v.y * wt),
                    "f"(v.z * wt), "f"(v.w * wt) : "memory");
}

// 2 pairs per thread: one int4 index load + one float2 distance load
// (fully vectorized, coalesced), 4 independent charge gathers in flight,
// 4 fire-and-forget vectorized L2 reductions. ~28 regs -> full occupancy.
__global__ void __launch_bounds__(256) pair_scatter_kernel(
    const float4* __restrict__ charges,     // N_ATOMS
    const int4*   __restrict__ nbr_idx4,    // N_PAIRS/2 (one int4 = 2 pairs)
    const float2* __restrict__ nbr_dist2,   // N_PAIRS/2
    float4*       __restrict__ potential)   // N_ATOMS
{
    int t = blockIdx.x * blockDim.x + threadIdx.x;
    if (t >= N_PAIRS / PPT) return;

    // Streaming loads (touched exactly once).
    int4   ij = __ldcs(&nbr_idx4[t]);   // (i0, j0, i1, j1)
    float2 dv = __ldcs(&nbr_dist2[t]);

    float w0 = __fdividef(0.5f, dv.x);
    float w1 = __fdividef(0.5f, dv.y);

    // All 4 gathers in flight before any consumer.
    float4 ci0 = __ldg(&charges[ij.x]);
    float4 cj0 = __ldg(&charges[ij.y]);
    float4 ci1 = __ldg(&charges[ij.z]);
    float4 cj1 = __ldg(&charges[ij.w]);

    red4(potential + ij.x, cj0, w0);
    red4(potential + ij.y, ci0, w0);
    red4(potential + ij.z, cj1, w1);
    red4(potential + ij.w, ci1, w1);
}

extern "C" void kernel_launch(void* const* d_in, const int* in_sizes, int n_in,
                              void* d_out, int out_size)
{
    const float4* charges   = (const float4*)d_in[0];  // N_ATOMS*4 f32
    const int4*   nbr_idx4  = (const int4*)d_in[1];    // N_PAIRS*2 i32
    const float2* nbr_dist2 = (const float2*)d_in[2];  // N_PAIRS f32
    float4*       out       = (float4*)d_out;          // N_ATOMS*4 f32

    // Output is accumulated into; zero it (memset node is graph-capturable).
    cudaMemsetAsync(d_out, 0, (size_t)out_size * sizeof(float));

    const int threads = 256;
    const int nthreads_total = N_PAIRS / PPT;          // 4,000,000
    const int blocks = (nthreads_total + threads - 1) / threads;
    pair_scatter_kernel<<<blocks, threads>>>(charges, nbr_idx4, nbr_dist2, out);
}

// round 9
// speedup vs baseline: 1.0195x; 1.0021x over previous
#include <cuda_runtime.h>
#include <cuda_bf16.h>
#include <cstdint>

// Problem constants (match reference)
#define N_ATOMS 200000
#define N_PAIRS 8000000
#define N_CH 4
#define PPT 2   // pairs per thread

__device__ __forceinline__ void red4(float4* ptr, float4 v, float wt)
{
    asm volatile("red.global.add.v4.f32 [%0], {%1, %2, %3, %4};"
                 :: "l"(ptr), "f"(v.x * wt), "f"(v.y * wt),
                    "f"(v.z * wt), "f"(v.w * wt) : "memory");
}

// L1-no-allocate 16B gather (random gathers get ~0 reuse; keep L1tex light).
__device__ __forceinline__ float4 ldcg4(const float4* p)
{
    float4 r;
    asm volatile("ld.global.cg.v4.f32 {%0, %1, %2, %3}, [%4];"
                 : "=f"(r.x), "=f"(r.y), "=f"(r.z), "=f"(r.w) : "l"(p));
    return r;
}

// 2 pairs per thread: one int4 index load + one float2 distance load
// (fully vectorized, coalesced). Per-pair gather->RED scheduling keeps
// register live ranges short (higher achieved occupancy) while the LSU
// queue stays full.
__global__ void __launch_bounds__(512) pair_scatter_kernel(
    const float4* __restrict__ charges,     // N_ATOMS
    const int4*   __restrict__ nbr_idx4,    // N_PAIRS/2 (one int4 = 2 pairs)
    const float2* __restrict__ nbr_dist2,   // N_PAIRS/2
    float4*       __restrict__ potential)   // N_ATOMS
{
    int t = blockIdx.x * blockDim.x + threadIdx.x;
    if (t >= N_PAIRS / PPT) return;

    // Streaming loads (touched exactly once).
    int4   ij = __ldcs(&nbr_idx4[t]);   // (i0, j0, i1, j1)
    float2 dv = __ldcs(&nbr_dist2[t]);

    float w0 = __fdividef(0.5f, dv.x);
    float w1 = __fdividef(0.5f, dv.y);

    // Pair 0
    float4 ci0 = ldcg4(&charges[ij.x]);
    float4 cj0 = ldcg4(&charges[ij.y]);
    // Pair 1 gathers issued before pair-0 REDs consume (keeps 4 loads in flight)
    float4 ci1 = ldcg4(&charges[ij.z]);
    float4 cj1 = ldcg4(&charges[ij.w]);

    red4(potential + ij.x, cj0, w0);
    red4(potential + ij.y, ci0, w0);
    red4(potential + ij.z, cj1, w1);
    red4(potential + ij.w, ci1, w1);
}

extern "C" void kernel_launch(void* const* d_in, const int* in_sizes, int n_in,
                              void* d_out, int out_size)
{
    const float4* charges   = (const float4*)d_in[0];  // N_ATOMS*4 f32
    const int4*   nbr_idx4  = (const int4*)d_in[1];    // N_PAIRS*2 i32
    const float2* nbr_dist2 = (const float2*)d_in[2];  // N_PAIRS f32
    float4*       out       = (float4*)d_out;          // N_ATOMS*4 f32

    // Output is accumulated into; zero it (memset node is graph-capturable).
    cudaMemsetAsync(d_out, 0, (size_t)out_size * sizeof(float));

    const int threads = 512;
    const int nthreads_total = N_PAIRS / PPT;          // 4,000,000
    const int blocks = (nthreads_total + threads - 1) / threads;
    pair_scatter_kernel<<<blocks, threads>>>(charges, nbr_idx4, nbr_dist2, out);
}

// round 11
// speedup vs baseline: 1.0221x; 1.0026x over previous
#include <cuda_runtime.h>
#include <cuda_bf16.h>
#include <cstdint>

// Problem constants (match reference)
#define N_ATOMS 200000
#define N_PAIRS 8000000
#define N_CH 4

__device__ __forceinline__ void red4(float4* ptr, float4 v, float wt)
{
    asm volatile("red.global.add.v4.f32 [%0], {%1, %2, %3, %4};"
                 :: "l"(ptr), "f"(v.x * wt), "f"(v.y * wt),
                    "f"(v.z * wt), "f"(v.w * wt) : "memory");
}

// L1-no-allocate 16B gather (random gathers over a 3.2MB L2-resident table:
// ~0 L1 reuse, keep the L1tex pipeline light).
__device__ __forceinline__ float4 ldcg4(const float4* p)
{
    float4 r;
    asm volatile("ld.global.cg.v4.f32 {%0, %1, %2, %3}, [%4];"
                 : "=f"(r.x), "=f"(r.y), "=f"(r.z), "=f"(r.w) : "l"(p));
    return r;
}

// One pair per thread (best-measured config: max warps, 20 regs, minimal
// per-CTA front-batched LDG count -> minimal L1tex queue spread).
// 2 random gathers + 2 vectorized fire-and-forget L2 reductions per pair.
__global__ void __launch_bounds__(256) pair_scatter_kernel(
    const float4* __restrict__ charges,     // N_ATOMS
    const int2*   __restrict__ nbr_idx,     // N_PAIRS
    const float*  __restrict__ nbr_dist,    // N_PAIRS
    float4*       __restrict__ potential)   // N_ATOMS
{
    int p = blockIdx.x * blockDim.x + threadIdx.x;
    if (p >= N_PAIRS) return;

    int2  ij = __ldcs(&nbr_idx[p]);     // streamed once
    float d  = __ldcs(&nbr_dist[p]);    // streamed once
    float w  = __fdividef(0.5f, d);     // MUFU.RCP path; |err| ~2^-22 << 1e-3

    float4 ci = ldcg4(&charges[ij.x]);
    float4 cj = ldcg4(&charges[ij.y]);

    red4(potential + ij.x, cj, w);
    red4(potential + ij.y, ci, w);
}

extern "C" void kernel_launch(void* const* d_in, const int* in_sizes, int n_in,
                              void* d_out, int out_size)
{
    const float4* charges  = (const float4*)d_in[0];  // N_ATOMS*4 f32
    const int2*   nbr_idx  = (const int2*)d_in[1];    // N_PAIRS*2 i32
    const float*  nbr_dist = (const float*)d_in[2];   // N_PAIRS f32
    float4*       out      = (float4*)d_out;          // N_ATOMS*4 f32

    // Output is accumulated into; zero it (memset node is graph-capturable).
    cudaMemsetAsync(d_out, 0, (size_t)out_size * sizeof(float));

    const int threads = 256;
    const int blocks  = (N_PAIRS + threads - 1) / threads;
    pair_scatter_kernel<<<blocks, threads>>>(charges, nbr_idx, nbr_dist, out);
}